// round 3
// baseline (speedup 1.0000x reference)
#include <cuda_runtime.h>
#include <cstdint>

#define QNL 6

struct cpx { float x, y; };
__device__ __forceinline__ cpx cmul(cpx a, cpx b){ return cpx{a.x*b.x - a.y*b.y, a.x*b.y + a.y*b.x}; }
__device__ __forceinline__ cpx cadd(cpx a, cpx b){ return cpx{a.x + b.x, a.y + b.y}; }

// Fully fused: warp 0 of every block computes the 29 model coefficients
// (exact closed form of the 2-qubit circuits), publishes to shared, then all
// threads stream the batch.
//
// Coefficient block sC[]:
// [0]      K (constant term incl. b2[1]-b2[0] and both circuits' identity terms)
// [1..8]   circuit-1 coeffs for {cb, sb, ca, ca*cb, ca*sb, sa, sa*cb, sa*sb}
// [9..16]  circuit-2 coeffs, same order
// [17..28] angle affine maps: 4 rows of (w_x0, w_x1, bias) for a1,b1,a2,b2
__global__ __launch_bounds__(256) void hybrid_fused(
    const float4* __restrict__ xin, float4* __restrict__ out, int half,
    const float* __restrict__ qw1, const float* __restrict__ qw2,
    const float* __restrict__ W1,  const float* __restrict__ b1,
    const float* __restrict__ W2,  const float* __restrict__ b2)
{
    __shared__ float sC[32];
    __shared__ cpx U[2][4][4];
    __shared__ cpx M[2][2][4][4];
    __shared__ float Kpart[2];

    if (threadIdx.x < 32){
        int t = threadIdx.x;
        int c = t >> 4;          // circuit
        int e = t & 15;          // matrix entry
        int I = e >> 2, J = e & 3;
        const float* qw = c ? qw2 : qw1;

        U[c][I][J] = cpx{ (I == J) ? 1.0f : 0.0f, 0.0f };
        __syncwarp();

        // CNOT(q0->q1) permutes rows 2<->3; fold into which T-row we compute.
        int S  = (I < 2) ? I : (5 - I);
        int iS = S >> 1, jS = S & 1;

        for (int l = 0; l < QNL; l++){
            float s0, c0, s1, c1;
            __sincosf(qw[2*l + 0] * 0.5f, &s0, &c0);
            __sincosf(qw[2*l + 1] * 0.5f, &s1, &c1);
            cpx T = cpx{0.f, 0.f};
            #pragma unroll
            for (int K = 0; K < 4; K++){
                int kS = K >> 1, lS = K & 1;
                cpx r0 = (iS == kS) ? cpx{c0, 0.f} : cpx{0.f, -s0};
                cpx r1 = (jS == lS) ? cpx{c1, 0.f} : cpx{0.f, -s1};
                T = cadd(T, cmul(cmul(r0, r1), U[c][K][J]));
            }
            __syncwarp();
            U[c][I][J] = T;
            __syncwarp();
        }

        // M_m = U^dag D_m U, D0 = diag(1,1,-1,-1), D1 = diag(1,-1,1,-1)
        cpx m0 = cpx{0.f,0.f}, m1 = cpx{0.f,0.f};
        #pragma unroll
        for (int K = 0; K < 4; K++){
            cpx a = U[c][K][I];
            cpx b = U[c][K][J];
            cpx tK = cmul(cpx{a.x, -a.y}, b);
            float d0 = (K < 2)  ?  1.f : -1.f;
            float d1 = (K & 1)  ? -1.f :  1.f;
            m0.x += d0*tK.x; m0.y += d0*tK.y;
            m1.x += d1*tK.x; m1.y += d1*tK.y;
        }
        M[c][0][I][J] = m0;
        M[c][1][I][J] = m1;
        __syncwarp();

        if (e < 9){
            int alpha = e / 3, beta = e % 3;  // 0=I, 1=Z(cos), 2=Y(sin)
            float C0 = 0.f, C1 = 0.f;
            #pragma unroll
            for (int ra = 0; ra < 2; ra++){
                int ia = ra;
                int ka = (alpha == 2) ? 1 - ra : ra;
                cpx va = (alpha == 0) ? cpx{1.f, 0.f}
                       : (alpha == 1) ? cpx{ra ? -1.f : 1.f, 0.f}
                                      : cpx{0.f, ra ? 1.f : -1.f};
                #pragma unroll
                for (int rb = 0; rb < 2; rb++){
                    int ib = rb;
                    int kb = (beta == 2) ? 1 - rb : rb;
                    cpx vb = (beta == 0) ? cpx{1.f, 0.f}
                           : (beta == 1) ? cpx{rb ? -1.f : 1.f, 0.f}
                                         : cpx{0.f, rb ? 1.f : -1.f};
                    cpx v = cmul(va, vb);
                    cpx e0 = M[c][0][2*ia + ib][2*ka + kb];
                    cpx e1 = M[c][1][2*ia + ib][2*ka + kb];
                    C0 += v.x*e0.x - v.y*e0.y;
                    C1 += v.x*e1.x - v.y*e1.y;
                }
            }
            float w0 = W2[4 + 2*c + 0] - W2[2*c + 0];
            float w1 = W2[4 + 2*c + 1] - W2[2*c + 1];
            float g = 0.25f * (w0*C0 + w1*C1);
            if (e == 0) Kpart[c] = g;
            else        sC[8*c + e] = g;
        }
        __syncwarp();
        if (t == 0) sC[0] = (b2[1] - b2[0]) + Kpart[0] + Kpart[1];
        if (t < 12) sC[17 + t] = ((t % 3) == 2) ? b1[t / 3] : W1[(t / 3) * 2 + (t % 3)];
    }
    __syncthreads();

    int t = blockIdx.x * blockDim.x + threadIdx.x;
    if (t >= half) return;

    // Main streaming phase: 2 float4 loads = 4 batch elements per thread.
    float4 v0 = __ldg(&xin[t]);
    float4 v1 = __ldg(&xin[t + half]);

    float4 r[2];
    float4 vv[2] = { v0, v1 };
    #pragma unroll
    for (int k = 0; k < 2; k++){
        float res[4];
        #pragma unroll
        for (int h = 0; h < 2; h++){
            float x0 = h ? vv[k].z : vv[k].x;
            float x1 = h ? vv[k].w : vv[k].y;
            float a1 = fmaf(sC[17], x0, fmaf(sC[18], x1, sC[19]));
            float b1v= fmaf(sC[20], x0, fmaf(sC[21], x1, sC[22]));
            float a2 = fmaf(sC[23], x0, fmaf(sC[24], x1, sC[25]));
            float b2v= fmaf(sC[26], x0, fmaf(sC[27], x1, sC[28]));
            float sa1, ca1, sb1, cb1, sa2, ca2, sb2, cb2;
            __sincosf(a1,  &sa1, &ca1);
            __sincosf(b1v, &sb1, &cb1);
            __sincosf(a2,  &sa2, &ca2);
            __sincosf(b2v, &sb2, &cb2);

            float q1 = fmaf(sC[1], cb1, fmaf(sC[2],  sb1, sC[0]));
            float p1 = ca1 * fmaf(sC[4],  cb1, fmaf(sC[5],  sb1, sC[3]));
            float p2 = sa1 * fmaf(sC[7],  cb1, fmaf(sC[8],  sb1, sC[6]));
            float q2 = fmaf(sC[9], cb2, sC[10] * sb2);
            float p3 = ca2 * fmaf(sC[12], cb2, fmaf(sC[13], sb2, sC[11]));
            float p4 = sa2 * fmaf(sC[15], cb2, fmaf(sC[16], sb2, sC[14]));

            float d = (q1 + p1) + (p2 + q2) + (p3 + p4);

            // softmax over 2 logits, d = l1 - l0:  p0 = 1/(1+e^d), p1 = e^d * p0
            float ed = __expf(d);
            float rr = __fdividef(1.0f, 1.0f + ed);
            res[2*h]     = rr;
            res[2*h + 1] = ed * rr;
        }
        r[k] = make_float4(res[0], res[1], res[2], res[3]);
    }
    out[t]        = r[0];
    out[t + half] = r[1];
}

extern "C" void kernel_launch(void* const* d_in, const int* in_sizes, int n_in,
                              void* d_out, int out_size){
    const float* x   = (const float*)d_in[0];
    const float* W1  = (const float*)d_in[1];
    const float* b1  = (const float*)d_in[2];
    const float* qw1 = (const float*)d_in[3];
    const float* qw2 = (const float*)d_in[4];
    const float* W2  = (const float*)d_in[5];
    const float* b2  = (const float*)d_in[6];

    int nf4  = in_sizes[0] / 4;       // one float4 = 2 batch elements
    int half = nf4 / 2;               // each thread handles 2 float4s (4 elements)
    int grid = (half + 255) / 256;
    hybrid_fused<<<grid, 256>>>((const float4*)x, (float4*)d_out, half,
                                qw1, qw2, W1, b1, W2, b2);
}

// round 4
// speedup vs baseline: 1.1359x; 1.1359x over previous
#include <cuda_runtime.h>
#include <cstdint>

#define QNL 6

struct cpx { float x, y; };
__device__ __forceinline__ cpx cmul(cpx a, cpx b){ return cpx{a.x*b.x - a.y*b.y, a.x*b.y + a.y*b.x}; }
__device__ __forceinline__ cpx cadd(cpx a, cpx b){ return cpx{a.x + b.x, a.y + b.y}; }

// Persistent fused kernel: one wave of blocks; warp 0 of each block computes the
// 29 model coefficients once (exact closed form of both 2-qubit circuits),
// publishes to shared, then all threads stream the whole batch grid-stride.
//
// sC[]:
// [0]      K (constant incl. b2[1]-b2[0] and both circuits' identity terms)
// [1..8]   circuit-1 coeffs {cb, sb, ca, ca*cb, ca*sb, sa, sa*cb, sa*sb}
// [9..16]  circuit-2 coeffs, same order
// [17..28] angle affine maps: 4 rows of (w_x0, w_x1, bias) for a1,b1,a2,b2
__global__ __launch_bounds__(256) void hybrid_fused(
    const float4* __restrict__ xin, float4* __restrict__ out, int half,
    const float* __restrict__ qw1, const float* __restrict__ qw2,
    const float* __restrict__ W1,  const float* __restrict__ b1,
    const float* __restrict__ W2,  const float* __restrict__ b2)
{
    __shared__ float sC[32];
    __shared__ cpx U[2][4][4];
    __shared__ cpx M[2][2][4][4];
    __shared__ float qs[24], qc[24];      // sin/cos of half-angles, [circuit*12 + 2l + w]
    __shared__ float sW2[8];
    __shared__ float sKb2;
    __shared__ float Kpart[2];

    const int nthreads = gridDim.x * blockDim.x;
    int i0 = blockIdx.x * blockDim.x + threadIdx.x;

    // ---- prefetch first tile before the barrier (overlaps prelude) ----
    float4 v0, v1;
    bool valid = i0 < half;
    if (valid){
        v0 = __ldg(&xin[i0]);
        v1 = __ldg(&xin[i0 + half]);
    }

    if (threadIdx.x < 32){
        int t = threadIdx.x;
        int c = t >> 4;          // circuit
        int e = t & 15;          // matrix entry
        int I = e >> 2, J = e & 3;

        // parallel parameter fetch: one round trip for everything
        if (t < 24){
            float th = (t < 12) ? qw1[t] : qw2[t - 12];
            float s, cc;
            __sincosf(th * 0.5f, &s, &cc);
            qs[t] = s; qc[t] = cc;
        }
        if (t < 12) sC[17 + t] = ((t % 3) == 2) ? b1[t / 3] : W1[(t / 3) * 2 + (t % 3)];
        if (t >= 24) sW2[t - 24] = W2[t - 24];
        if (t == 23) sKb2 = b2[1] - b2[0];

        U[c][I][J] = cpx{ (I == J) ? 1.0f : 0.0f, 0.0f };
        __syncwarp();

        // CNOT(q0->q1) permutes rows 2<->3; fold into which T-row we compute.
        int S  = (I < 2) ? I : (5 - I);
        int iS = S >> 1, jS = S & 1;

        for (int l = 0; l < QNL; l++){
            float c0 = qc[c*12 + 2*l],     s0 = qs[c*12 + 2*l];
            float c1 = qc[c*12 + 2*l + 1], s1 = qs[c*12 + 2*l + 1];
            cpx T = cpx{0.f, 0.f};
            #pragma unroll
            for (int K = 0; K < 4; K++){
                int kS = K >> 1, lS = K & 1;
                cpx r0 = (iS == kS) ? cpx{c0, 0.f} : cpx{0.f, -s0};
                cpx r1 = (jS == lS) ? cpx{c1, 0.f} : cpx{0.f, -s1};
                T = cadd(T, cmul(cmul(r0, r1), U[c][K][J]));
            }
            __syncwarp();
            U[c][I][J] = T;
            __syncwarp();
        }

        // M_m = U^dag D_m U, D0 = diag(1,1,-1,-1), D1 = diag(1,-1,1,-1)
        cpx m0 = cpx{0.f,0.f}, m1 = cpx{0.f,0.f};
        #pragma unroll
        for (int K = 0; K < 4; K++){
            cpx a = U[c][K][I];
            cpx b = U[c][K][J];
            cpx tK = cmul(cpx{a.x, -a.y}, b);
            float d0 = (K < 2)  ?  1.f : -1.f;
            float d1 = (K & 1)  ? -1.f :  1.f;
            m0.x += d0*tK.x; m0.y += d0*tK.y;
            m1.x += d1*tK.x; m1.y += d1*tK.y;
        }
        M[c][0][I][J] = m0;
        M[c][1][I][J] = m1;
        __syncwarp();

        if (e < 9){
            int alpha = e / 3, beta = e % 3;  // 0=I, 1=Z(cos), 2=Y(sin)
            float C0 = 0.f, C1 = 0.f;
            #pragma unroll
            for (int ra = 0; ra < 2; ra++){
                int ia = ra;
                int ka = (alpha == 2) ? 1 - ra : ra;
                cpx va = (alpha == 0) ? cpx{1.f, 0.f}
                       : (alpha == 1) ? cpx{ra ? -1.f : 1.f, 0.f}
                                      : cpx{0.f, ra ? 1.f : -1.f};
                #pragma unroll
                for (int rb = 0; rb < 2; rb++){
                    int ib = rb;
                    int kb = (beta == 2) ? 1 - rb : rb;
                    cpx vb = (beta == 0) ? cpx{1.f, 0.f}
                           : (beta == 1) ? cpx{rb ? -1.f : 1.f, 0.f}
                                         : cpx{0.f, rb ? 1.f : -1.f};
                    cpx v = cmul(va, vb);
                    cpx e0 = M[c][0][2*ia + ib][2*ka + kb];
                    cpx e1 = M[c][1][2*ia + ib][2*ka + kb];
                    C0 += v.x*e0.x - v.y*e0.y;
                    C1 += v.x*e1.x - v.y*e1.y;
                }
            }
            float w0 = sW2[4 + 2*c + 0] - sW2[2*c + 0];
            float w1 = sW2[4 + 2*c + 1] - sW2[2*c + 1];
            float g = 0.25f * (w0*C0 + w1*C1);
            if (e == 0) Kpart[c] = g;
            else        sC[8*c + e] = g;
        }
        __syncwarp();
        if (t == 0) sC[0] = sKb2 + Kpart[0] + Kpart[1];
    }
    __syncthreads();

    // ---- streaming phase: software-pipelined grid-stride over float4 pairs ----
    int i = i0;
    while (valid){
        int inext = i + nthreads;
        bool vnext = inext < half;
        float4 n0, n1;
        if (vnext){
            n0 = __ldg(&xin[inext]);
            n1 = __ldg(&xin[inext + half]);
        }

        float4 vv[2] = { v0, v1 };
        float4 r[2];
        #pragma unroll
        for (int k = 0; k < 2; k++){
            float res[4];
            #pragma unroll
            for (int h = 0; h < 2; h++){
                float x0 = h ? vv[k].z : vv[k].x;
                float x1 = h ? vv[k].w : vv[k].y;
                float a1 = fmaf(sC[17], x0, fmaf(sC[18], x1, sC[19]));
                float b1v= fmaf(sC[20], x0, fmaf(sC[21], x1, sC[22]));
                float a2 = fmaf(sC[23], x0, fmaf(sC[24], x1, sC[25]));
                float b2v= fmaf(sC[26], x0, fmaf(sC[27], x1, sC[28]));
                float sa1, ca1, sb1, cb1, sa2, ca2, sb2, cb2;
                __sincosf(a1,  &sa1, &ca1);
                __sincosf(b1v, &sb1, &cb1);
                __sincosf(a2,  &sa2, &ca2);
                __sincosf(b2v, &sb2, &cb2);

                float q1 = fmaf(sC[1], cb1, fmaf(sC[2],  sb1, sC[0]));
                float p1 = ca1 * fmaf(sC[4],  cb1, fmaf(sC[5],  sb1, sC[3]));
                float p2 = sa1 * fmaf(sC[7],  cb1, fmaf(sC[8],  sb1, sC[6]));
                float q2 = fmaf(sC[9], cb2, sC[10] * sb2);
                float p3 = ca2 * fmaf(sC[12], cb2, fmaf(sC[13], sb2, sC[11]));
                float p4 = sa2 * fmaf(sC[15], cb2, fmaf(sC[16], sb2, sC[14]));

                float d = (q1 + p1) + (p2 + q2) + (p3 + p4);

                // softmax over 2 logits, d = l1 - l0: p0 = 1/(1+e^d), p1 = e^d * p0
                float ed = __expf(d);
                float rr = __fdividef(1.0f, 1.0f + ed);
                res[2*h]     = rr;
                res[2*h + 1] = ed * rr;
            }
            r[k] = make_float4(res[0], res[1], res[2], res[3]);
        }
        out[i]        = r[0];
        out[i + half] = r[1];

        i = inext; valid = vnext; v0 = n0; v1 = n1;
    }
}

extern "C" void kernel_launch(void* const* d_in, const int* in_sizes, int n_in,
                              void* d_out, int out_size){
    const float* x   = (const float*)d_in[0];
    const float* W1  = (const float*)d_in[1];
    const float* b1  = (const float*)d_in[2];
    const float* qw1 = (const float*)d_in[3];
    const float* qw2 = (const float*)d_in[4];
    const float* W2  = (const float*)d_in[5];
    const float* b2  = (const float*)d_in[6];

    int nf4  = in_sizes[0] / 4;       // one float4 = 2 batch elements
    int half = nf4 / 2;               // each thread iteration: 2 float4s = 4 elements
    int grid = 148 * 5;               // one wave at 48 regs / 256 threads
    hybrid_fused<<<grid, 256>>>((const float4*)x, (float4*)d_out, half,
                                qw1, qw2, W1, b1, W2, b2);
}

// round 5
// speedup vs baseline: 1.1848x; 1.0430x over previous
#include <cuda_runtime.h>
#include <cstdint>

#define QNL 6

struct cpx { float x, y; };
__device__ __forceinline__ cpx cmul(cpx a, cpx b){ return cpx{a.x*b.x - a.y*b.y, a.x*b.y + a.y*b.x}; }
__device__ __forceinline__ cpx cadd(cpx a, cpx b){ return cpx{a.x + b.x, a.y + b.y}; }

__device__ __forceinline__ float tanh_approx(float x){
    float y;
    asm("tanh.approx.f32 %0, %1;" : "=f"(y) : "f"(x));
    return y;
}

// Persistent fused kernel, one wave. Warp 0 of each block computes the 29 model
// coefficients once (exact closed form of both 2-qubit circuits), publishes to
// shared; all 256 threads then stream the batch grid-stride at full occupancy.
//
// sC[]:
// [0]      K (constant incl. b2[1]-b2[0] and both circuits' identity terms)
// [1..8]   circuit-1 coeffs {cb, sb, ca, ca*cb, ca*sb, sa, sa*cb, sa*sb}
// [9..16]  circuit-2 coeffs, same order
// [17..28] angle affine maps: 4 rows of (w_x0, w_x1, bias) for a1,b1,a2,b2
__global__ __launch_bounds__(256, 8) void hybrid_fused(
    const float4* __restrict__ xin, float4* __restrict__ out, int nf4,
    const float* __restrict__ qw1, const float* __restrict__ qw2,
    const float* __restrict__ W1,  const float* __restrict__ b1,
    const float* __restrict__ W2,  const float* __restrict__ b2)
{
    __shared__ float sC[32];
    __shared__ cpx U[2][4][4];
    __shared__ cpx M[2][2][4][4];
    __shared__ float qs[24], qc[24];
    __shared__ float sW2[8];
    __shared__ float sKb2;
    __shared__ float Kpart[2];

    if (threadIdx.x < 32){
        int t = threadIdx.x;
        int c = t >> 4;          // circuit
        int e = t & 15;          // matrix entry
        int I = e >> 2, J = e & 3;

        // parallel parameter fetch: one round trip for everything
        if (t < 24){
            float th = (t < 12) ? qw1[t] : qw2[t - 12];
            float s, cc;
            __sincosf(th * 0.5f, &s, &cc);
            qs[t] = s; qc[t] = cc;
        }
        if (t < 12) sC[17 + t] = ((t % 3) == 2) ? b1[t / 3] : W1[(t / 3) * 2 + (t % 3)];
        if (t >= 24) sW2[t - 24] = W2[t - 24];
        if (t == 23) sKb2 = b2[1] - b2[0];

        U[c][I][J] = cpx{ (I == J) ? 1.0f : 0.0f, 0.0f };
        __syncwarp();

        // CNOT(q0->q1) permutes rows 2<->3; fold into which T-row we compute.
        int S  = (I < 2) ? I : (5 - I);
        int iS = S >> 1, jS = S & 1;

        for (int l = 0; l < QNL; l++){
            float c0 = qc[c*12 + 2*l],     s0 = qs[c*12 + 2*l];
            float c1 = qc[c*12 + 2*l + 1], s1 = qs[c*12 + 2*l + 1];
            cpx T = cpx{0.f, 0.f};
            #pragma unroll
            for (int K = 0; K < 4; K++){
                int kS = K >> 1, lS = K & 1;
                cpx r0 = (iS == kS) ? cpx{c0, 0.f} : cpx{0.f, -s0};
                cpx r1 = (jS == lS) ? cpx{c1, 0.f} : cpx{0.f, -s1};
                T = cadd(T, cmul(cmul(r0, r1), U[c][K][J]));
            }
            __syncwarp();
            U[c][I][J] = T;
            __syncwarp();
        }

        // M_m = U^dag D_m U, D0 = diag(1,1,-1,-1), D1 = diag(1,-1,1,-1)
        cpx m0 = cpx{0.f,0.f}, m1 = cpx{0.f,0.f};
        #pragma unroll
        for (int K = 0; K < 4; K++){
            cpx a = U[c][K][I];
            cpx b = U[c][K][J];
            cpx tK = cmul(cpx{a.x, -a.y}, b);
            float d0 = (K < 2)  ?  1.f : -1.f;
            float d1 = (K & 1)  ? -1.f :  1.f;
            m0.x += d0*tK.x; m0.y += d0*tK.y;
            m1.x += d1*tK.x; m1.y += d1*tK.y;
        }
        M[c][0][I][J] = m0;
        M[c][1][I][J] = m1;
        __syncwarp();

        if (e < 9){
            int alpha = e / 3, beta = e % 3;  // 0=I, 1=Z(cos), 2=Y(sin)
            float C0 = 0.f, C1 = 0.f;
            #pragma unroll
            for (int ra = 0; ra < 2; ra++){
                int ia = ra;
                int ka = (alpha == 2) ? 1 - ra : ra;
                cpx va = (alpha == 0) ? cpx{1.f, 0.f}
                       : (alpha == 1) ? cpx{ra ? -1.f : 1.f, 0.f}
                                      : cpx{0.f, ra ? 1.f : -1.f};
                #pragma unroll
                for (int rb = 0; rb < 2; rb++){
                    int ib = rb;
                    int kb = (beta == 2) ? 1 - rb : rb;
                    cpx vb = (beta == 0) ? cpx{1.f, 0.f}
                           : (beta == 1) ? cpx{rb ? -1.f : 1.f, 0.f}
                                         : cpx{0.f, rb ? 1.f : -1.f};
                    cpx v = cmul(va, vb);
                    cpx e0 = M[c][0][2*ia + ib][2*ka + kb];
                    cpx e1 = M[c][1][2*ia + ib][2*ka + kb];
                    C0 += v.x*e0.x - v.y*e0.y;
                    C1 += v.x*e1.x - v.y*e1.y;
                }
            }
            float w0 = sW2[4 + 2*c + 0] - sW2[2*c + 0];
            float w1 = sW2[4 + 2*c + 1] - sW2[2*c + 1];
            float g = 0.25f * (w0*C0 + w1*C1);
            if (e == 0) Kpart[c] = g;
            else        sC[8*c + e] = g;
        }
        __syncwarp();
        if (t == 0) sC[0] = sKb2 + Kpart[0] + Kpart[1];
    }
    __syncthreads();

    // ---- streaming phase: one float4 (2 batch elements) per iteration ----
    const int stride = gridDim.x * blockDim.x;
    for (int i = blockIdx.x * blockDim.x + threadIdx.x; i < nf4; i += stride){
        float4 v = __ldg(&xin[i]);
        float res[4];
        #pragma unroll
        for (int h = 0; h < 2; h++){
            float x0 = h ? v.z : v.x;
            float x1 = h ? v.w : v.y;
            float a1 = fmaf(sC[17], x0, fmaf(sC[18], x1, sC[19]));
            float b1v= fmaf(sC[20], x0, fmaf(sC[21], x1, sC[22]));
            float a2 = fmaf(sC[23], x0, fmaf(sC[24], x1, sC[25]));
            float b2v= fmaf(sC[26], x0, fmaf(sC[27], x1, sC[28]));
            float sa1, ca1, sb1, cb1, sa2, ca2, sb2, cb2;
            __sincosf(a1,  &sa1, &ca1);
            __sincosf(b1v, &sb1, &cb1);
            __sincosf(a2,  &sa2, &ca2);
            __sincosf(b2v, &sb2, &cb2);

            float q1 = fmaf(sC[1], cb1, fmaf(sC[2],  sb1, sC[0]));
            float p1 = ca1 * fmaf(sC[4],  cb1, fmaf(sC[5],  sb1, sC[3]));
            float p2 = sa1 * fmaf(sC[7],  cb1, fmaf(sC[8],  sb1, sC[6]));
            float q2 = fmaf(sC[9], cb2, sC[10] * sb2);
            float p3 = ca2 * fmaf(sC[12], cb2, fmaf(sC[13], sb2, sC[11]));
            float p4 = sa2 * fmaf(sC[15], cb2, fmaf(sC[16], sb2, sC[14]));

            float d = (q1 + p1) + (p2 + q2) + (p3 + p4);

            // softmax over 2 logits, d = l1 - l0:
            // p0 = 0.5 - 0.5*tanh(d/2), p1 = 0.5 + 0.5*tanh(d/2)
            float th = tanh_approx(0.5f * d);
            res[2*h]     = fmaf(-0.5f, th, 0.5f);
            res[2*h + 1] = fmaf( 0.5f, th, 0.5f);
        }
        out[i] = make_float4(res[0], res[1], res[2], res[3]);
    }
}

extern "C" void kernel_launch(void* const* d_in, const int* in_sizes, int n_in,
                              void* d_out, int out_size){
    const float* x   = (const float*)d_in[0];
    const float* W1  = (const float*)d_in[1];
    const float* b1  = (const float*)d_in[2];
    const float* qw1 = (const float*)d_in[3];
    const float* qw2 = (const float*)d_in[4];
    const float* W2  = (const float*)d_in[5];
    const float* b2  = (const float*)d_in[6];

    int nf4  = in_sizes[0] / 4;       // one float4 = 2 batch elements
    int grid = 148 * 8;               // one full wave at 32 regs / 256 threads
    hybrid_fused<<<grid, 256>>>((const float4*)x, (float4*)d_out, nf4,
                                qw1, qw2, W1, b1, W2, b2);
}